// round 2
// baseline (speedup 1.0000x reference)
#include <cuda_runtime.h>
#include <math.h>

// Problem constants
#define N_ 128
#define K_ 64
#define C_ 64
#define ROWS_ (N_ * K_)   // 8192

// Scratch (device globals: no allocation allowed)
__device__ float g_U [ROWS_ * C_];   // um * ug
__device__ float g_A [ROWS_ * C_];   // h @ Wb1[:C]  + bb1
__device__ float g_B [ROWS_ * C_];   // h @ Wb1[C:]
__device__ float g_Ag[ROWS_ * C_];   // h @ Wbg1[:C] + bbg1
__device__ float g_Bg[ROWS_ * C_];   // h @ Wbg1[C:]

__device__ __forceinline__ float fast_tanh(float x) {
    // tanh(x) = 1 - 2/(exp(2x)+1); exp->inf and exp->0 limits are exact.
    return 1.0f - __fdividef(2.0f, __expf(2.0f * x) + 1.0f);
}
__device__ __forceinline__ float fast_sigmoid(float x) {
    return __fdividef(1.0f, 1.0f + __expf(-x));
}

// ---------------------------------------------------------------------------
// Kernel 1: per row r of h (8192 rows):
//   h = x @ W_lin + b_lin
//   U = (tanh(h@Wu1+bu1)@Wu2+bu2) * sigmoid(tanh(h@Wug1+bug1)@Wug2+bug2)
//   A = h@Wb1a + bb1 ; B = h@Wb1b ; Ag = h@Wbg1a + bbg1 ; Bg = h@Wbg1b
// 128 blocks x 64 rows, 256 threads (4 rows x 64 channels per pass).
// Dynamic smem: 9 weight matrices (64x64) + x/h/t row buffers.
// ---------------------------------------------------------------------------
#define PREP_SMEM_FLOATS (9 * 4096 + 3 * 256)

__global__ __launch_bounds__(256)
void prep_kernel(const float* __restrict__ x,
                 const float* __restrict__ Wlin, const float* __restrict__ blin,
                 const float* __restrict__ Wu1,  const float* __restrict__ bu1,
                 const float* __restrict__ Wu2,  const float* __restrict__ bu2,
                 const float* __restrict__ Wug1, const float* __restrict__ bug1,
                 const float* __restrict__ Wug2, const float* __restrict__ bug2,
                 const float* __restrict__ Wb1,  const float* __restrict__ bb1,
                 const float* __restrict__ Wbg1, const float* __restrict__ bbg1)
{
    extern __shared__ float sm[];
    float* sWlin  = sm;
    float* sWu1   = sm + 4096;
    float* sWu2   = sm + 2 * 4096;
    float* sWug1  = sm + 3 * 4096;
    float* sWug2  = sm + 4 * 4096;
    float* sWb1a  = sm + 5 * 4096;
    float* sWb1b  = sm + 6 * 4096;
    float* sWbg1a = sm + 7 * 4096;
    float* sWbg1b = sm + 8 * 4096;
    float* sx     = sm + 9 * 4096;         // [4][64]
    float* sh     = sx + 256;              // [4][64]
    float* st     = sh + 256;              // [4][64]

    const int tid = threadIdx.x;
    for (int i = tid; i < 4096; i += 256) {
        sWlin[i]  = Wlin[i];
        sWu1[i]   = Wu1[i];
        sWu2[i]   = Wu2[i];
        sWug1[i]  = Wug1[i];
        sWug2[i]  = Wug2[i];
        sWb1a[i]  = Wb1[i];
        sWb1b[i]  = Wb1[4096 + i];
        sWbg1a[i] = Wbg1[i];
        sWbg1b[i] = Wbg1[4096 + i];
    }
    __syncthreads();

    const int rr = tid >> 6;     // 0..3 row-in-group
    const int c  = tid & 63;     // channel
    const int row0 = blockIdx.x * 64;

    for (int g = 0; g < 16; g++) {
        const int row = row0 + g * 4 + rr;
        sx[rr * 64 + c] = x[row * 64 + c];
        __syncthreads();

        // h = x @ Wlin + blin
        float acc = blin[c];
        #pragma unroll 16
        for (int k = 0; k < 64; k++)
            acc = fmaf(sx[rr * 64 + k], sWlin[k * 64 + c], acc);
        sh[rr * 64 + c] = acc;
        __syncthreads();

        // unary passing: t1 = tanh(h@Wu1+bu1)
        acc = bu1[c];
        #pragma unroll 16
        for (int k = 0; k < 64; k++)
            acc = fmaf(sh[rr * 64 + k], sWu1[k * 64 + c], acc);
        st[rr * 64 + c] = fast_tanh(acc);
        __syncthreads();

        // um = t1 @ Wu2 + bu2
        float um = bu2[c];
        #pragma unroll 16
        for (int k = 0; k < 64; k++)
            um = fmaf(st[rr * 64 + k], sWu2[k * 64 + c], um);
        __syncthreads();   // before st is overwritten

        // unary gate: t2 = tanh(h@Wug1+bug1)
        acc = bug1[c];
        #pragma unroll 16
        for (int k = 0; k < 64; k++)
            acc = fmaf(sh[rr * 64 + k], sWug1[k * 64 + c], acc);
        st[rr * 64 + c] = fast_tanh(acc);
        __syncthreads();

        // ug = sigmoid(t2 @ Wug2 + bug2)
        float ug = bug2[c];
        #pragma unroll 16
        for (int k = 0; k < 64; k++)
            ug = fmaf(st[rr * 64 + k], sWug2[k * 64 + c], ug);
        ug = fast_sigmoid(ug);

        g_U[row * 64 + c] = um * ug;

        // binary first-layer factors
        float a  = bb1[c];
        float b  = 0.0f;
        float ag = bbg1[c];
        float bg = 0.0f;
        #pragma unroll 16
        for (int k = 0; k < 64; k++) {
            const float hv = sh[rr * 64 + k];
            a  = fmaf(hv, sWb1a [k * 64 + c], a);
            b  = fmaf(hv, sWb1b [k * 64 + c], b);
            ag = fmaf(hv, sWbg1a[k * 64 + c], ag);
            bg = fmaf(hv, sWbg1b[k * 64 + c], bg);
        }
        g_A [row * 64 + c] = a;
        g_B [row * 64 + c] = b;
        g_Ag[row * 64 + c] = ag;
        g_Bg[row * 64 + c] = bg;
        __syncthreads();   // before sx/sh reuse
    }
}

// ---------------------------------------------------------------------------
// Kernel 2: one block per (n, group of 4 j's). 2048 blocks, 256 threads.
// For each j:
//   T[k][i]  = tanh(A[n,j][k] + B[n,i][k])      (smem, transposed, pad 68)
//   Tg[k][i] = tanh(Ag[n,j][k] + Bg[n,i][k])
//   Mb = T^T @ Wb2 ; Mg = Tg^T @ Wbg2            (64x64x64 GEMMs, 4x4 reg tiles)
//   out[n,j,c] = U[n,j,c] + (1/63) * sum_i (Mb[i,c]+bb2[c]) * sig(Mg[i,c]+bbg2[c])
// ---------------------------------------------------------------------------
#define TPAD 68
#define MAIN_SMEM_FLOATS (4 * 4096 + 2 * 64 * TPAD + 2 * 256 + 16 * 64)

__global__ __launch_bounds__(256, 2)
void main_kernel(const float* __restrict__ Wb2,  const float* __restrict__ bb2,
                 const float* __restrict__ Wbg2, const float* __restrict__ bbg2,
                 float* __restrict__ out)
{
    extern __shared__ float sm[];
    float* sW2  = sm;                       // [64][64]
    float* sWg2 = sm + 4096;                // [64][64]
    float* sB   = sm + 2 * 4096;            // [64][64]  (i-major)
    float* sBg  = sm + 3 * 4096;            // [64][64]
    float* sT   = sm + 4 * 4096;            // [64][TPAD] (k-major, i contiguous)
    float* sTg  = sT + 64 * TPAD;           // [64][TPAD]
    float* sA   = sTg + 64 * TPAD;          // [4][64]
    float* sAg  = sA + 256;                 // [4][64]
    float* sred = sAg + 256;                // [16][64]

    const int tid = threadIdx.x;
    const int n   = blockIdx.x >> 4;
    const int jg  = blockIdx.x & 15;

    // block-wide loads
    for (int i = tid; i < 4096; i += 256) {
        sW2 [i] = Wb2[i];
        sWg2[i] = Wbg2[i];
        sB  [i] = g_B [n * 4096 + i];
        sBg [i] = g_Bg[n * 4096 + i];
    }
    sA [tid] = g_A [n * 4096 + jg * 256 + tid];
    sAg[tid] = g_Ag[n * 4096 + jg * 256 + tid];
    __syncthreads();

    const int ti = tid >> 4;     // 0..15 -> i-tile (4 rows)
    const int tc = tid & 15;     // 0..15 -> c-tile (4 cols)
    const int kk = tid & 63;     // phase-1: channel k
    const int id4 = tid >> 6;    // phase-1: i offset 0..3

    float bb2r[4], bbg2r[4];
    #pragma unroll
    for (int s = 0; s < 4; s++) {
        bb2r [s] = bb2 [4 * tc + s];
        bbg2r[s] = bbg2[4 * tc + s];
    }

    for (int jj = 0; jj < 4; jj++) {
        // ---- phase 1: build T, Tg (transposed: [k][i]) ----
        const float aj  = sA [jj * 64 + kk];
        const float agj = sAg[jj * 64 + kk];
        #pragma unroll
        for (int it = 0; it < 16; it++) {
            const int i = it * 4 + id4;
            sT [kk * TPAD + i] = fast_tanh(aj  + sB [i * 64 + kk]);
            sTg[kk * TPAD + i] = fast_tanh(agj + sBg[i * 64 + kk]);
        }
        __syncthreads();

        // ---- phase 2: two 64x64x64 GEMMs, 4x4 register tile each ----
        float accb[4][4];
        float accg[4][4];
        #pragma unroll
        for (int r = 0; r < 4; r++)
            #pragma unroll
            for (int s = 0; s < 4; s++) { accb[r][s] = 0.0f; accg[r][s] = 0.0f; }

        #pragma unroll 8
        for (int k = 0; k < 64; k++) {
            const float4 ab  = *(const float4*)(sT  + k * TPAD + 4 * ti);
            const float4 agv = *(const float4*)(sTg + k * TPAD + 4 * ti);
            const float4 wb  = *(const float4*)(sW2  + k * 64 + 4 * tc);
            const float4 wg  = *(const float4*)(sWg2 + k * 64 + 4 * tc);
            const float abr[4] = {ab.x,  ab.y,  ab.z,  ab.w};
            const float agr[4] = {agv.x, agv.y, agv.z, agv.w};
            const float wbr[4] = {wb.x,  wb.y,  wb.z,  wb.w};
            const float wgr[4] = {wg.x,  wg.y,  wg.z,  wg.w};
            #pragma unroll
            for (int r = 0; r < 4; r++) {
                #pragma unroll
                for (int s = 0; s < 4; s++) {
                    accb[r][s] = fmaf(abr[r], wbr[s], accb[r][s]);
                    accg[r][s] = fmaf(agr[r], wgr[s], accg[r][s]);
                }
            }
        }

        // ---- phase 3: gate + partial i-reduction ----
        #pragma unroll
        for (int s = 0; s < 4; s++) {
            float p = 0.0f;
            #pragma unroll
            for (int r = 0; r < 4; r++) {
                const float gate = fast_sigmoid(accg[r][s] + bbg2r[s]);
                p = fmaf(accb[r][s] + bb2r[s], gate, p);
            }
            sred[ti * 64 + 4 * tc + s] = p;
        }
        __syncthreads();

        if (tid < 64) {
            float sum = 0.0f;
            #pragma unroll
            for (int u = 0; u < 16; u++) sum += sred[u * 64 + tid];
            const int j = jg * 4 + jj;
            const int o = (n * 64 + j) * 64 + tid;
            out[o] = g_U[o] + sum * (1.0f / 63.0f);
        }
        __syncthreads();   // sred / sT reuse next jj
    }
}

// ---------------------------------------------------------------------------
// launch
// ---------------------------------------------------------------------------
extern "C" void kernel_launch(void* const* d_in, const int* in_sizes, int n_in,
                              void* d_out, int out_size)
{
    const float* x    = (const float*)d_in[0];
    const float* Wlin = (const float*)d_in[1];
    const float* blin = (const float*)d_in[2];
    const float* Wu1  = (const float*)d_in[3];
    const float* bu1  = (const float*)d_in[4];
    const float* Wu2  = (const float*)d_in[5];
    const float* bu2  = (const float*)d_in[6];
    const float* Wug1 = (const float*)d_in[7];
    const float* bug1 = (const float*)d_in[8];
    const float* Wug2 = (const float*)d_in[9];
    const float* bug2 = (const float*)d_in[10];
    const float* Wb1  = (const float*)d_in[11];
    const float* bb1  = (const float*)d_in[12];
    const float* Wb2  = (const float*)d_in[13];
    const float* bb2  = (const float*)d_in[14];
    const float* Wbg1 = (const float*)d_in[15];
    const float* bbg1 = (const float*)d_in[16];
    const float* Wbg2 = (const float*)d_in[17];
    const float* bbg2 = (const float*)d_in[18];
    // d_in[19] = t (ignored by IgnoreLinear)

    float* out = (float*)d_out;

    const int prep_smem = PREP_SMEM_FLOATS * (int)sizeof(float);   // 150528 B
    const int main_smem = MAIN_SMEM_FLOATS * (int)sizeof(float);   // 106496 B
    cudaFuncSetAttribute(prep_kernel, cudaFuncAttributeMaxDynamicSharedMemorySize, prep_smem);
    cudaFuncSetAttribute(main_kernel, cudaFuncAttributeMaxDynamicSharedMemorySize, main_smem);

    prep_kernel<<<128, 256, prep_smem>>>(x, Wlin, blin, Wu1, bu1, Wu2, bu2,
                                         Wug1, bug1, Wug2, bug2,
                                         Wb1, bb1, Wbg1, bbg1);
    main_kernel<<<2048, 256, main_smem>>>(Wb2, bb2, Wbg2, bbg2, out);
}